// round 2
// baseline (speedup 1.0000x reference)
#include <cuda_runtime.h>
#include <math.h>
#include <stdint.h>

// Problem constants
#define S_ 8192
#define D_ 2048
#define H_ 64
#define E_ 64
#define L_ 64

#define NPART 256            // colsum partial blocks (32 rows each)
#define KSPLIT 2
#define KHALF (D_ / KSPLIT)  // 1024
#define KC 16                // k-chunk staged in smem

// Static device scratch (no allocation allowed)
__device__ float g_vpart[NPART][D_];
__device__ float g_gate[2];
__device__ int   g_idx[2];
__device__ float g_cpart[KSPLIT][S_][128];   // split-K GEMM partials (8.4 MB)

// ---------------------------------------------------------------------------
// packed fp32x2 helpers (Blackwell FFMA2 — only reachable via PTX)
// ---------------------------------------------------------------------------
__device__ __forceinline__ void fma2(uint64_t& c, uint64_t a, uint64_t b) {
    asm("fma.rn.f32x2 %0, %1, %2, %0;" : "+l"(c) : "l"(a), "l"(b));
}
__device__ __forceinline__ uint64_t dup2(uint32_t x) {
    uint64_t r;
    asm("mov.b64 %0, {%1, %2};" : "=l"(r) : "r"(x), "r"(x));
    return r;
}

// ---------------------------------------------------------------------------
// Kernel 1: weighted column sums of x: vpart[b][d] = sum_{32 rows} wout[s]*x[s][d]
// 256 blocks x 32 rows; thread t owns 8 contiguous columns.
// ---------------------------------------------------------------------------
__global__ void __launch_bounds__(256) k_colsum(const float* __restrict__ x,
                                                const float* __restrict__ wout) {
    __shared__ float ws[32];
    const int b = blockIdx.x;
    const int t = threadIdx.x;
    const int row0 = b * 32;
    if (t < 32) ws[t] = wout[row0 + t];
    __syncthreads();

    const int d0 = t * 8;
    float acc[8];
#pragma unroll
    for (int i = 0; i < 8; i++) acc[i] = 0.f;

    const float* xp = x + (size_t)row0 * D_ + d0;
#pragma unroll 8
    for (int r = 0; r < 32; r++) {
        const float w = ws[r];
        const float4 a = *(const float4*)(xp);
        const float4 c = *(const float4*)(xp + 4);
        acc[0] = fmaf(w, a.x, acc[0]);
        acc[1] = fmaf(w, a.y, acc[1]);
        acc[2] = fmaf(w, a.z, acc[2]);
        acc[3] = fmaf(w, a.w, acc[3]);
        acc[4] = fmaf(w, c.x, acc[4]);
        acc[5] = fmaf(w, c.y, acc[5]);
        acc[6] = fmaf(w, c.z, acc[6]);
        acc[7] = fmaf(w, c.w, acc[7]);
        xp += D_;
    }
#pragma unroll
    for (int i = 0; i < 8; i++) g_vpart[b][d0 + i] = acc[i];
}

// ---------------------------------------------------------------------------
// Kernel 2: finish the gate (v reduce, two matvecs, top-2, softmax)
// ---------------------------------------------------------------------------
__global__ void __launch_bounds__(256) k_gate(const float* __restrict__ Wg_in,
                                              const float* __restrict__ Wg_lin) {
    __shared__ float v[D_];
    __shared__ float u[H_];
    __shared__ float sc[E_];
    const int t = threadIdx.x;

    for (int d = t; d < D_; d += 256) {
        float s = 0.f;
#pragma unroll 8
        for (int b = 0; b < NPART; b++) s += g_vpart[b][d];
        v[d] = s;
    }
    __syncthreads();

    const int w = t >> 5, lane = t & 31;
    for (int jj = 0; jj < 8; jj++) {
        const int j = w * 8 + jj;
        const float* wr = Wg_in + (size_t)j * D_;
        float s = 0.f;
#pragma unroll 8
        for (int d = lane; d < D_; d += 32) s = fmaf(wr[d], v[d], s);
#pragma unroll
        for (int off = 16; off; off >>= 1) s += __shfl_down_sync(0xffffffffu, s, off);
        if (lane == 0) u[j] = s;
    }
    __syncthreads();

    if (t < E_) {
        float s = 0.f;
#pragma unroll
        for (int j = 0; j < H_; j++) s = fmaf(Wg_lin[t * H_ + j], u[j], s);
        sc[t] = s;
    }
    __syncthreads();

    if (t == 0) {
        int i0 = 0;
        for (int e = 1; e < E_; e++) if (sc[e] > sc[i0]) i0 = e;
        int i1 = (i0 == 0) ? 1 : 0;
        for (int e = 0; e < E_; e++) {
            if (e == i0 || e == i1) continue;
            if (sc[e] > sc[i1]) i1 = e;
        }
        const float m = sc[i0];
        const float e0 = expf(sc[i0] - m);
        const float e1 = expf(sc[i1] - m);
        const float inv = 1.f / (e0 + e1);
        g_gate[0] = e0 * inv;
        g_gate[1] = e1 * inv;
        g_idx[0] = i0;
        g_idx[1] = i1;
    }
}

// ---------------------------------------------------------------------------
// Kernel 3: split-K expert GEMM with packed f32x2 FMA.
//   C[s, 0:64] = x[s,:].We[idx0]^T ; C[s, 64:128] = x[s,:].We[idx1]^T
// Tile 128x128, 256 threads, 8x8 micro-tile, accumulators packed over row
// pairs. Kc=16 double-buffered smem, reg-staged transpose loads.
// grid = 64 row tiles x 2 K-splits = 128 CTAs.
// ---------------------------------------------------------------------------
__global__ void __launch_bounds__(256) k_expert(const float* __restrict__ x,
                                                const float* __restrict__ We) {
    __shared__ union {
        struct { float A[2][KC][128]; float B[2][KC][128]; } s;  // 32 KB
        float C[64][128];                                         // 32 KB
    } sm;

    const int t = threadIdx.x;
    const int rt = blockIdx.x >> 1;        // row tile 0..63
    const int ks = blockIdx.x & 1;         // k split 0..1
    const int row0 = rt * 128;
    const int kbase = ks * KHALF;
    const int i0 = g_idx[0], i1 = g_idx[1];

    // global load mapping: lrow = row/col index, lkg selects k-subgroup of 8
    const int lrow = t & 127;
    const int lkg = t >> 7;                // 0 or 1
    const float* aptr = x + (size_t)(row0 + lrow) * D_ + kbase + lkg * 8;
    const int eidx = (lrow < 64) ? i0 : i1;
    const float* bptr = We + ((size_t)eidx * L_ + (lrow & 63)) * D_ + kbase + lkg * 8;

    // compute fragment mapping: 16x16 thread grid, 8x8 micro-tile
    const int tm = (t >> 4) * 8;           // row base 0..120
    const int tn = (t & 15) * 8;           // col base 0..120

    uint64_t c[4][8];
#pragma unroll
    for (int p = 0; p < 4; p++)
#pragma unroll
        for (int j = 0; j < 8; j++) c[p][j] = 0ull;

    // prologue: chunk 0 -> regs -> smem buf 0
    float4 pa0 = *(const float4*)(aptr);
    float4 pa1 = *(const float4*)(aptr + 4);
    float4 pb0 = *(const float4*)(bptr);
    float4 pb1 = *(const float4*)(bptr + 4);
    {
        const int kb = lkg * 8;
        sm.s.A[0][kb + 0][lrow] = pa0.x; sm.s.A[0][kb + 1][lrow] = pa0.y;
        sm.s.A[0][kb + 2][lrow] = pa0.z; sm.s.A[0][kb + 3][lrow] = pa0.w;
        sm.s.A[0][kb + 4][lrow] = pa1.x; sm.s.A[0][kb + 5][lrow] = pa1.y;
        sm.s.A[0][kb + 6][lrow] = pa1.z; sm.s.A[0][kb + 7][lrow] = pa1.w;
        sm.s.B[0][kb + 0][lrow] = pb0.x; sm.s.B[0][kb + 1][lrow] = pb0.y;
        sm.s.B[0][kb + 2][lrow] = pb0.z; sm.s.B[0][kb + 3][lrow] = pb0.w;
        sm.s.B[0][kb + 4][lrow] = pb1.x; sm.s.B[0][kb + 5][lrow] = pb1.y;
        sm.s.B[0][kb + 6][lrow] = pb1.z; sm.s.B[0][kb + 7][lrow] = pb1.w;
    }
    __syncthreads();

    const int NC = KHALF / KC;  // 64 chunks
    int cur = 0;
#pragma unroll 1
    for (int ch = 0; ch < NC; ++ch) {
        // prefetch next chunk to regs while computing this one
        if (ch + 1 < NC) {
            const float* ap = aptr + (ch + 1) * KC;
            pa0 = *(const float4*)(ap);
            pa1 = *(const float4*)(ap + 4);
            const float* bp = bptr + (ch + 1) * KC;
            pb0 = *(const float4*)(bp);
            pb1 = *(const float4*)(bp + 4);
        }

#pragma unroll
        for (int kk = 0; kk < KC; ++kk) {
            // a: 4 natural row-pairs (rows tm..tm+7)
            const ulonglong2 qa0 = *(const ulonglong2*)&sm.s.A[cur][kk][tm];
            const ulonglong2 qa1 = *(const ulonglong2*)&sm.s.A[cur][kk][tm + 4];
            uint64_t ap4[4] = { qa0.x, qa0.y, qa1.x, qa1.y };
            // b: 8 scalars, duplicated into f32x2 (MOVs ride the alu pipe)
            const uint4 qb0 = *(const uint4*)&sm.s.B[cur][kk][tn];
            const uint4 qb1 = *(const uint4*)&sm.s.B[cur][kk][tn + 4];
            uint64_t bd[8];
            bd[0] = dup2(qb0.x); bd[1] = dup2(qb0.y);
            bd[2] = dup2(qb0.z); bd[3] = dup2(qb0.w);
            bd[4] = dup2(qb1.x); bd[5] = dup2(qb1.y);
            bd[6] = dup2(qb1.z); bd[7] = dup2(qb1.w);
#pragma unroll
            for (int p = 0; p < 4; p++)
#pragma unroll
                for (int j = 0; j < 8; j++) fma2(c[p][j], ap4[p], bd[j]);
        }

        // stage next chunk into the other buffer (its last readers synced out
        // at the end of chunk ch-1)
        if (ch + 1 < NC) {
            const int nb = cur ^ 1;
            const int kb = lkg * 8;
            sm.s.A[nb][kb + 0][lrow] = pa0.x; sm.s.A[nb][kb + 1][lrow] = pa0.y;
            sm.s.A[nb][kb + 2][lrow] = pa0.z; sm.s.A[nb][kb + 3][lrow] = pa0.w;
            sm.s.A[nb][kb + 4][lrow] = pa1.x; sm.s.A[nb][kb + 5][lrow] = pa1.y;
            sm.s.A[nb][kb + 6][lrow] = pa1.z; sm.s.A[nb][kb + 7][lrow] = pa1.w;
            sm.s.B[nb][kb + 0][lrow] = pb0.x; sm.s.B[nb][kb + 1][lrow] = pb0.y;
            sm.s.B[nb][kb + 2][lrow] = pb0.z; sm.s.B[nb][kb + 3][lrow] = pb0.w;
            sm.s.B[nb][kb + 4][lrow] = pb1.x; sm.s.B[nb][kb + 5][lrow] = pb1.y;
            sm.s.B[nb][kb + 6][lrow] = pb1.z; sm.s.B[nb][kb + 7][lrow] = pb1.w;
        }
        __syncthreads();
        cur ^= 1;
    }

    // epilogue: stage C through smem (two 64-row halves), coalesced STG.128
#pragma unroll 1
    for (int h = 0; h < 2; ++h) {
        if ((tm >> 6) == h) {
            const int rb = tm - h * 64;
#pragma unroll
            for (int p = 0; p < 4; p++)
#pragma unroll
                for (int j = 0; j < 8; j++) {
                    const uint64_t v = c[p][j];
                    sm.C[rb + 2 * p][tn + j]     = __uint_as_float((uint32_t)v);
                    sm.C[rb + 2 * p + 1][tn + j] = __uint_as_float((uint32_t)(v >> 32));
                }
        }
        __syncthreads();
        for (int i = t; i < 64 * 32; i += 256) {
            const int r = i >> 5, c4 = i & 31;
            *(float4*)&g_cpart[ks][row0 + h * 64 + r][c4 * 4] =
                *(const float4*)&sm.C[r][c4 * 4];
        }
        __syncthreads();
    }
}

// ---------------------------------------------------------------------------
// Kernel 4: reduce K-splits, normalize per expert, exact GELU, gated combine.
// One warp per row, grid 1024 x 256 threads.
// ---------------------------------------------------------------------------
__device__ __forceinline__ float gelu_exact(float x) {
    return 0.5f * x * (1.f + erff(x * 0.70710678118654752440f));
}

__global__ void __launch_bounds__(256) k_finish(float* __restrict__ out) {
    const int row = blockIdx.x * 8 + (threadIdx.x >> 5);
    const int lane = threadIdx.x & 31;

    const float z0a = g_cpart[0][row][lane]      + g_cpart[1][row][lane];
    const float z0b = g_cpart[0][row][lane + 32] + g_cpart[1][row][lane + 32];
    const float z1a = g_cpart[0][row][lane + 64] + g_cpart[1][row][lane + 64];
    const float z1b = g_cpart[0][row][lane + 96] + g_cpart[1][row][lane + 96];

    float ss0 = z0a * z0a + z0b * z0b;
    float ss1 = z1a * z1a + z1b * z1b;
#pragma unroll
    for (int off = 16; off; off >>= 1) {
        ss0 += __shfl_xor_sync(0xffffffffu, ss0, off);
        ss1 += __shfl_xor_sync(0xffffffffu, ss1, off);
    }
    const float inv0 = 1.f / fmaxf(sqrtf(ss0), 1e-12f);
    const float inv1 = 1.f / fmaxf(sqrtf(ss1), 1e-12f);
    const float g0 = g_gate[0], g1 = g_gate[1];

    float* orow = out + (size_t)row * L_;
    orow[lane]      = g0 * gelu_exact(z0a * inv0) + g1 * gelu_exact(z1a * inv1);
    orow[lane + 32] = g0 * gelu_exact(z0b * inv0) + g1 * gelu_exact(z1b * inv1);
}

// ---------------------------------------------------------------------------
extern "C" void kernel_launch(void* const* d_in, const int* in_sizes, int n_in,
                              void* d_out, int out_size) {
    const float* x      = (const float*)d_in[0];
    const float* Wg_in  = (const float*)d_in[1];
    const float* Wg_lin = (const float*)d_in[2];
    const float* Wg_out = (const float*)d_in[3];
    const float* We     = (const float*)d_in[4];
    float* out = (float*)d_out;

    k_colsum<<<NPART, 256>>>(x, Wg_out);
    k_gate<<<1, 256>>>(Wg_in, Wg_lin);
    k_expert<<<128, 256>>>(x, We);
    k_finish<<<S_ / 8, 256>>>(out);
}

// round 4
// speedup vs baseline: 2.1111x; 2.1111x over previous
#include <cuda_runtime.h>
#include <math.h>
#include <stdint.h>

// Problem constants
#define S_ 8192
#define D_ 2048
#define H_ 64
#define E_ 64
#define L_ 64

#define NPART 256
#define BM 64
#define BN 128
#define KC 32
#define NCH (D_ / KC)      // 64
#define RS 40              // smem row stride in bf16 elems (80 B, conflict-free)

// Static device scratch
__device__ __align__(16) float g_vpart[NPART][D_];
__device__ __align__(16) float g_v[D_];
__device__ __align__(16) float g_u[H_];
__device__ float g_gate[2];
__device__ int   g_idx[2];

// ===========================================================================
// helpers
// ===========================================================================
__device__ __forceinline__ uint32_t smem_u32(const void* p) {
    uint32_t a;
    asm("{ .reg .u64 t; cvta.to.shared.u64 t, %1; cvt.u32.u64 %0, t; }"
        : "=r"(a) : "l"(p));
    return a;
}

// bf16 hi/lo split of 2 floats: hi = rn(f), lo = rn(f - hi), packed bf16x2
// (low half of the packed word = lower k index)
__device__ __forceinline__ void cvt_split(float f0, float f1, uint32_t& hi, uint32_t& lo) {
    uint32_t h;
    asm("cvt.rn.bf16x2.f32 %0, %1, %2;" : "=r"(h) : "f"(f1), "f"(f0));
    const float l0 = f0 - __uint_as_float(h << 16);
    const float l1 = f1 - __uint_as_float(h & 0xFFFF0000u);
    uint32_t l;
    asm("cvt.rn.bf16x2.f32 %0, %1, %2;" : "=r"(l) : "f"(l1), "f"(l0));
    hi = h; lo = l;
}

__device__ __forceinline__ void ldsm4(uint32_t* r, uint32_t addr) {
    asm volatile("ldmatrix.sync.aligned.m8n8.x4.shared.b16 {%0,%1,%2,%3}, [%4];"
                 : "=r"(r[0]), "=r"(r[1]), "=r"(r[2]), "=r"(r[3]) : "r"(addr));
}

__device__ __forceinline__ void mma_bf16(float* c, const uint32_t* a, const uint32_t* b) {
    asm volatile("mma.sync.aligned.m16n8k16.row.col.f32.bf16.bf16.f32 "
                 "{%0,%1,%2,%3}, {%4,%5,%6,%7}, {%8,%9}, {%0,%1,%2,%3};"
                 : "+f"(c[0]), "+f"(c[1]), "+f"(c[2]), "+f"(c[3])
                 : "r"(a[0]), "r"(a[1]), "r"(a[2]), "r"(a[3]), "r"(b[0]), "r"(b[1]));
}

__device__ __forceinline__ float gelu_exact(float v) {
    return 0.5f * v * (1.f + erff(v * 0.70710678118654752440f));
}

// ===========================================================================
// Kernel 1: weighted column sums: vpart[b][d] = sum_{32 rows} wout[s]*x[s][d]
// ===========================================================================
__global__ void __launch_bounds__(256) k_colsum(const float* __restrict__ x,
                                                const float* __restrict__ wout) {
    __shared__ float ws[32];
    const int b = blockIdx.x, t = threadIdx.x;
    const int row0 = b * 32;
    if (t < 32) ws[t] = wout[row0 + t];
    __syncthreads();

    const int d0 = t * 8;
    float acc[8];
#pragma unroll
    for (int i = 0; i < 8; i++) acc[i] = 0.f;
    const float* xp = x + (size_t)row0 * D_ + d0;
#pragma unroll 8
    for (int r = 0; r < 32; r++) {
        const float w = ws[r];
        const float4 a = *(const float4*)(xp);
        const float4 c = *(const float4*)(xp + 4);
        acc[0] = fmaf(w, a.x, acc[0]); acc[1] = fmaf(w, a.y, acc[1]);
        acc[2] = fmaf(w, a.z, acc[2]); acc[3] = fmaf(w, a.w, acc[3]);
        acc[4] = fmaf(w, c.x, acc[4]); acc[5] = fmaf(w, c.y, acc[5]);
        acc[6] = fmaf(w, c.z, acc[6]); acc[7] = fmaf(w, c.w, acc[7]);
        xp += D_;
    }
#pragma unroll
    for (int i = 0; i < 8; i++) g_vpart[b][d0 + i] = acc[i];
}

// ===========================================================================
// Kernel 2a: v[d] = sum_b vpart[b][d]
// ===========================================================================
__global__ void __launch_bounds__(256) k_vreduce() {
    const int d = blockIdx.x * 256 + threadIdx.x;
    float s = 0.f;
#pragma unroll 8
    for (int b = 0; b < NPART; b++) s += g_vpart[b][d];
    g_v[d] = s;
}

// ===========================================================================
// Kernel 2b: u = Wg_in @ v   (one warp per row)
// ===========================================================================
__global__ void __launch_bounds__(256) k_gate_u(const float* __restrict__ Wg_in) {
    const int wid = threadIdx.x >> 5, lane = threadIdx.x & 31;
    const int j = blockIdx.x * 8 + wid;
    const float* wr = Wg_in + (size_t)j * D_;
    float s = 0.f;
#pragma unroll
    for (int i = 0; i < 16; i++) {
        const float4 w = *(const float4*)(wr + i * 128 + lane * 4);
        const float4 v = *(const float4*)(&g_v[i * 128 + lane * 4]);
        s += w.x * v.x + w.y * v.y + w.z * v.z + w.w * v.w;
    }
#pragma unroll
    for (int off = 16; off; off >>= 1) s += __shfl_down_sync(0xffffffffu, s, off);
    if (lane == 0) g_u[j] = s;
}

// ===========================================================================
// Kernel 2c: scores = Wg_lin @ u; top-2 (low-index tie-break); softmax
// ===========================================================================
__global__ void __launch_bounds__(64) k_gate2(const float* __restrict__ Wg_lin) {
    __shared__ float sc[E_];
    __shared__ float u[H_];
    const int t = threadIdx.x;
    u[t] = g_u[t];
    __syncthreads();
    float s = 0.f;
#pragma unroll
    for (int j = 0; j < H_; j++) s = fmaf(Wg_lin[t * H_ + j], u[j], s);
    sc[t] = s;
    __syncthreads();
    if (t == 0) {
        int i0 = 0;
        for (int e = 1; e < E_; e++) if (sc[e] > sc[i0]) i0 = e;
        int i1 = (i0 == 0) ? 1 : 0;
        for (int e = 0; e < E_; e++) {
            if (e == i0 || e == i1) continue;
            if (sc[e] > sc[i1]) i1 = e;
        }
        const float e1 = expf(sc[i1] - sc[i0]);
        const float inv = 1.f / (1.f + e1);
        g_gate[0] = inv; g_gate[1] = e1 * inv;
        g_idx[0] = i0; g_idx[1] = i1;
    }
}

// ===========================================================================
// Kernel 3: HMMA expert GEMM (mma.sync bf16, 3-term split) + fused epilogue.
//   CTA: 64 rows x 128 cols (cols 0-63 expert0, 64-127 expert1).
//   8 warps in 2x4 grid; each warp 32x32 via m16n8k16.
// ===========================================================================
__global__ void __launch_bounds__(256) k_expert(const float* __restrict__ x,
                                                const float* __restrict__ We,
                                                float* __restrict__ out) {
    __shared__ union {
        struct {
            uint16_t Ahi[BM][RS];   // 5120 B
            uint16_t Alo[BM][RS];
            uint16_t Bhi[BN][RS];   // 10240 B
            uint16_t Blo[BN][RS];
        } t;
        float C[BM][BN];            // 32 KB
    } sm;

    const int t = threadIdx.x;
    const int wid = t >> 5, lane = t & 31;
    const int row0 = blockIdx.x * BM;
    const int i0 = g_idx[0], i1 = g_idx[1];

    // ---- global load mapping ----
    const int arow = t & 63, akg = t >> 6;            // A: row, k-group of 8
    const float* aptr = x + (size_t)(row0 + arow) * D_ + akg * 8;
    const int brow = t & 127, bkg = t >> 7;           // B: row, k-group of 16
    const int be = (brow < 64) ? i0 : i1;
    const float* bptr = We + ((size_t)be * L_ + (brow & 63)) * D_ + bkg * 16;

    uint16_t* sAhiW = &sm.t.Ahi[arow][akg * 8];
    uint16_t* sAloW = &sm.t.Alo[arow][akg * 8];
    uint16_t* sBhiW = &sm.t.Bhi[brow][bkg * 16];
    uint16_t* sBloW = &sm.t.Blo[brow][bkg * 16];

    // ---- compute fragment mapping ----
    const int warp_m = wid & 1, warp_n = wid >> 1;
    const int m_base = warp_m * 32, n_base = warp_n * 32;
    const int a_row = m_base + (lane & 15);
    const int a_k = (lane >> 4) << 3;
    const int b_row = n_base + ((lane >> 4) << 3) + (lane & 7);
    const int b_k = ((lane >> 3) & 1) << 3;

    const uint32_t aAhi = smem_u32(&sm.t.Ahi[a_row][a_k]);
    const uint32_t aAlo = smem_u32(&sm.t.Alo[a_row][a_k]);
    const uint32_t aBhi = smem_u32(&sm.t.Bhi[b_row][b_k]);
    const uint32_t aBlo = smem_u32(&sm.t.Blo[b_row][b_k]);

    float c[2][4][4];
#pragma unroll
    for (int mt = 0; mt < 2; mt++)
#pragma unroll
        for (int nt = 0; nt < 4; nt++)
#pragma unroll
            for (int r = 0; r < 4; r++) c[mt][nt][r] = 0.f;

    // ---- prologue: chunk 0 into regs ----
    float4 pa0 = *(const float4*)(aptr);
    float4 pa1 = *(const float4*)(aptr + 4);
    float4 pb0 = *(const float4*)(bptr);
    float4 pb1 = *(const float4*)(bptr + 4);
    float4 pb2 = *(const float4*)(bptr + 8);
    float4 pb3 = *(const float4*)(bptr + 12);

#pragma unroll 1
    for (int ch = 0; ch < NCH; ++ch) {
        // convert + store staged regs into smem tiles
        {
            uint4 hi, lo;
            cvt_split(pa0.x, pa0.y, hi.x, lo.x);
            cvt_split(pa0.z, pa0.w, hi.y, lo.y);
            cvt_split(pa1.x, pa1.y, hi.z, lo.z);
            cvt_split(pa1.z, pa1.w, hi.w, lo.w);
            *(uint4*)sAhiW = hi;
            *(uint4*)sAloW = lo;
            cvt_split(pb0.x, pb0.y, hi.x, lo.x);
            cvt_split(pb0.z, pb0.w, hi.y, lo.y);
            cvt_split(pb1.x, pb1.y, hi.z, lo.z);
            cvt_split(pb1.z, pb1.w, hi.w, lo.w);
            *(uint4*)sBhiW = hi;
            *(uint4*)sBloW = lo;
            cvt_split(pb2.x, pb2.y, hi.x, lo.x);
            cvt_split(pb2.z, pb2.w, hi.y, lo.y);
            cvt_split(pb3.x, pb3.y, hi.z, lo.z);
            cvt_split(pb3.z, pb3.w, hi.w, lo.w);
            *(uint4*)(sBhiW + 8) = hi;
            *(uint4*)(sBloW + 8) = lo;
        }
        __syncthreads();

        // prefetch next chunk while computing this one
        if (ch + 1 < NCH) {
            const float* ap = aptr + (ch + 1) * KC;
            pa0 = *(const float4*)(ap);
            pa1 = *(const float4*)(ap + 4);
            const float* bp = bptr + (ch + 1) * KC;
            pb0 = *(const float4*)(bp);
            pb1 = *(const float4*)(bp + 4);
            pb2 = *(const float4*)(bp + 8);
            pb3 = *(const float4*)(bp + 12);
        }

#pragma unroll
        for (int ks = 0; ks < 2; ks++) {
            const uint32_t kb = ks * 16 * 2;    // byte offset for k-step
            uint32_t ahi[2][4], alo[2][4], bhi[2][4], blo[2][4];
#pragma unroll
            for (int mt = 0; mt < 2; mt++) {
                ldsm4(ahi[mt], aAhi + mt * (16 * RS * 2) + kb);
                ldsm4(alo[mt], aAlo + mt * (16 * RS * 2) + kb);
            }
#pragma unroll
            for (int nn = 0; nn < 2; nn++) {
                ldsm4(bhi[nn], aBhi + nn * (16 * RS * 2) + kb);
                ldsm4(blo[nn], aBlo + nn * (16 * RS * 2) + kb);
            }
#pragma unroll
            for (int mt = 0; mt < 2; mt++)
#pragma unroll
                for (int nt = 0; nt < 4; nt++) {
                    const int nn = nt >> 1, hh = (nt & 1) * 2;
                    mma_bf16(c[mt][nt], ahi[mt], &bhi[nn][hh]);
                    mma_bf16(c[mt][nt], alo[mt], &bhi[nn][hh]);
                    mma_bf16(c[mt][nt], ahi[mt], &blo[nn][hh]);
                }
        }
        __syncthreads();
    }

    // ---- stage C into smem (union reuse; tiles fully consumed) ----
#pragma unroll
    for (int mt = 0; mt < 2; mt++)
#pragma unroll
        for (int nt = 0; nt < 4; nt++) {
            const int r0 = m_base + mt * 16 + (lane >> 2);
            const int c0 = n_base + nt * 8 + 2 * (lane & 3);
            *(float2*)&sm.C[r0][c0]     = make_float2(c[mt][nt][0], c[mt][nt][1]);
            *(float2*)&sm.C[r0 + 8][c0] = make_float2(c[mt][nt][2], c[mt][nt][3]);
        }
    __syncthreads();

    // ---- epilogue: per-row L2 norm per expert half, GELU, gated combine ----
    const float g0 = g_gate[0], g1 = g_gate[1];
#pragma unroll
    for (int r = 0; r < 8; r++) {
        const int row = wid * 8 + r;
        const float z0a = sm.C[row][lane];
        const float z0b = sm.C[row][lane + 32];
        const float z1a = sm.C[row][64 + lane];
        const float z1b = sm.C[row][96 + lane];
        float ss0 = z0a * z0a + z0b * z0b;
        float ss1 = z1a * z1a + z1b * z1b;
#pragma unroll
        for (int off = 16; off; off >>= 1) {
            ss0 += __shfl_xor_sync(0xffffffffu, ss0, off);
            ss1 += __shfl_xor_sync(0xffffffffu, ss1, off);
        }
        const float inv0 = 1.f / fmaxf(sqrtf(ss0), 1e-12f);
        const float inv1 = 1.f / fmaxf(sqrtf(ss1), 1e-12f);
        float* orow = out + (size_t)(row0 + row) * L_;
        orow[lane]      = g0 * gelu_exact(z0a * inv0) + g1 * gelu_exact(z1a * inv1);
        orow[lane + 32] = g0 * gelu_exact(z0b * inv0) + g1 * gelu_exact(z1b * inv1);
    }
}

// ===========================================================================
extern "C" void kernel_launch(void* const* d_in, const int* in_sizes, int n_in,
                              void* d_out, int out_size) {
    const float* x      = (const float*)d_in[0];
    const float* Wg_in  = (const float*)d_in[1];
    const float* Wg_lin = (const float*)d_in[2];
    const float* Wg_out = (const float*)d_in[3];
    const float* We     = (const float*)d_in[4];
    float* out = (float*)d_out;

    k_colsum<<<NPART, 256>>>(x, Wg_out);
    k_vreduce<<<8, 256>>>();
    k_gate_u<<<8, 256>>>(Wg_in);
    k_gate2<<<1, 64>>>(Wg_lin);
    k_expert<<<S_ / BM, 256>>>(x, We, out);
}